// round 15
// baseline (speedup 1.0000x reference)
#include <cuda_runtime.h>
#include <math.h>
#include <stdint.h>

#define GB       8
#define GH       32
#define GW       64
#define FULL_H   128
#define FULL_W   512
#define NFFT     1024
#define HOP      256
#define NK       513
#define NFRAMES  512
#define LSIG     130816
#define NSAMP    131072
#define NTOT     (GB*NFRAMES*NK)
#define OUT_AUDIO (GB*NSAMP)
#define OUT_FS    (GB*FULL_H*FULL_W)

#define FAST_START 4    /* GL iterations >= this use the radix-8 register FFT */

#define TWOPI_F  6.28318548202514648438f   /* f32(2*pi) */

// 9-bit bit reversal (pure permutation)
__device__ __forceinline__ int brev9(int i) { return __brev(i) >> 23; }

// ---------------------------------------------------------------------------
// Device scratch
// ---------------------------------------------------------------------------
__device__ float   g_win[NFFT];
__device__ float   g_win2[NFFT];
__device__ float   g_w2tab[256];      // interior OLA denominator (pre-guard)
__device__ float2  g_twdf1024[NK];    // e^{-2pi i k/1024}, f32 (rounded from f64)
__device__ float   g_mag[NTOT];
__device__ float2  g_S[NTOT];         // only used for initial spectrum
__device__ float2  g_T[NTOT];
__device__ float   g_frames[GB*NFRAMES*NFFT];
__device__ float   g_audio[GB*LSIG];
__device__ float   g_maxv[GB];

// ---------------------------------------------------------------------------
// Window value with EXACTLY the same f32 op sequence everywhere.
// ---------------------------------------------------------------------------
__device__ __forceinline__ float win_f32(int n) {
    float af = __fdiv_rn(__fmul_rn(TWOPI_F, (float)n), 1024.0f);
    float c  = (float)cos((double)af);
    return __fmul_rn(0.5f, __fsub_rn(1.0f, c));
}

__global__ void k_init_tables() {
    int i = blockIdx.x * blockDim.x + threadIdx.x;
    if (i < NFFT) {
        float w = win_f32(i);
        g_win[i]  = w;
        g_win2[i] = __fmul_rn(w, w);
    }
    if (i < NK) {
        double a = 2.0 * M_PI * (double)i / 1024.0;
        g_twdf1024[i] = make_float2((float)cos(a), (float)(-sin(a)));
    }
}

// Interior OLA denominator: same add chain as the scalar loop.
__global__ void k_init_w2tab() {
    int r = threadIdx.x;
    float w3 = win_f32(768 + r); w3 = __fmul_rn(w3, w3);
    float w2 = win_f32(512 + r); w2 = __fmul_rn(w2, w2);
    float w1 = win_f32(256 + r); w1 = __fmul_rn(w1, w1);
    float w0 = win_f32(r);       w0 = __fmul_rn(w0, w0);
    float s = __fadd_rn(0.0f, w3);
    s = __fadd_rn(s, w2);
    s = __fadd_rn(s, w1);
    s = __fadd_rn(s, w0);
    g_w2tab[r] = s;
}

// ---------------------------------------------------------------------------
// threefry2x32, key (0,1)
// ---------------------------------------------------------------------------
__device__ __forceinline__ unsigned rotl32(unsigned x, int r) {
    return (x << r) | (x >> (32 - r));
}
__device__ __forceinline__ uint2 threefry_01(unsigned c0, unsigned c1) {
    const unsigned k0 = 0u, k1 = 1u;
    const unsigned k2 = 0x1BD11BDAu ^ k0 ^ k1;
    unsigned x0 = c0 + k0, x1 = c1 + k1;
#define TFR(r) { x0 += x1; x1 = rotl32(x1, (r)); x1 ^= x0; }
    TFR(13) TFR(15) TFR(26) TFR(6)
    x0 += k1; x1 += k2 + 1u;
    TFR(17) TFR(29) TFR(16) TFR(24)
    x0 += k2; x1 += k0 + 2u;
    TFR(13) TFR(15) TFR(26) TFR(6)
    x0 += k0; x1 += k1 + 3u;
    TFR(17) TFR(29) TFR(16) TFR(24)
    x0 += k1; x1 += k2 + 4u;
    TFR(13) TFR(15) TFR(26) TFR(6)
    x0 += k2; x1 += k0 + 5u;
#undef TFR
    return make_uint2(x0, x1);
}

// ---------------------------------------------------------------------------
// EXACT 512-pt complex FFT, f32, 256 threads. Input already bit-reversed.
// This stage-loop body is load-bearing for bit-exactness — DO NOT RESTRUCTURE.
// ---------------------------------------------------------------------------
__device__ __forceinline__ void fft512f(float2* a, int tid, bool inverse) {
    #pragma unroll
    for (int s = 0; s < 9; s++) {
        int half = 1 << s;
        int pos  = tid & (half - 1);
        int i0   = ((tid >> s) << (s + 1)) + pos;
        int i1   = i0 + half;
        float2 t = g_twdf1024[pos << (9 - s)];
        float ty = inverse ? -t.y : t.y;
        float2 u = a[i0], v = a[i1];
        float vr = v.x * t.x - v.y * ty;
        float vi = v.x * ty + v.y * t.x;
        a[i0] = make_float2(u.x + vr, u.y + vi);
        a[i1] = make_float2(u.x - vr, u.y - vi);
        __syncthreads();
    }
}

// ---------------------------------------------------------------------------
// FAST 512-pt FFT: radix-8 register phases, 64 threads per FFT group.
// ---------------------------------------------------------------------------
__device__ __forceinline__ void bfly(float2& u, float2& v, float2 t, bool inverse) {
    float ty = inverse ? -t.y : t.y;
    float vr = v.x * t.x - v.y * ty;
    float vi = v.x * ty + v.y * t.x;
    float2 nu = make_float2(u.x + vr, u.y + vi);
    float2 nv = make_float2(u.x - vr, u.y - vi);
    u = nu; v = nv;
}

template <int S>
__device__ __forceinline__ void radix8_phase(float2* a, int t, bool inverse) {
    const int q = 1 << S;
    int base = ((t >> S) << (S + 3)) + (t & (q - 1));
    float2 x[8];
    #pragma unroll
    for (int j = 0; j < 8; j++) x[j] = a[base + j * q];
    #pragma unroll
    for (int k = 0; k < 3; k++) {
        int step = 1 << k;
        #pragma unroll
        for (int j = 0; j < 8; j++) {
            if ((j & step) == 0) {
                int pos = (t & (q - 1)) + q * (j & (step - 1));
                float2 tw = g_twdf1024[pos << (9 - S - k)];
                bfly(x[j], x[j + step], tw, inverse);
            }
        }
    }
    #pragma unroll
    for (int j = 0; j < 8; j++) a[base + j * q] = x[j];
}

// Group version: all 256 threads call this; each 64-thread group works on its
// own array `a`. Phase A->B is warp-local within the group (warp covers elems
// 0..255 of its group array in both phases); B->C and C->out are cross-warp,
// handled by uniform block-wide __syncthreads (no divergent barriers).
__device__ __forceinline__ void fft512f_fast_grp(float2* a, int t, bool inverse) {
    radix8_phase<0>(a, t, inverse);
    __syncwarp();
    radix8_phase<3>(a, t, inverse);
    __syncthreads();
    radix8_phase<6>(a, t, inverse);
    __syncthreads();
}

// ---------------------------------------------------------------------------
// Bilinear tap weights (compute_weight_mat f32 mimicry)
// ---------------------------------------------------------------------------
__device__ __forceinline__ void lin_weights(float p, int in_size,
                                            int& i0, int& i1,
                                            float& w0, float& w1) {
    int h0 = (int)floorf(p);
    int h1 = h0 + 1;
    float x0 = __fsub_rn(p, (float)h0);
    float x1 = __fsub_rn((float)h1, p);
    float a0 = (h0 >= 0 && h0 < in_size) ? __fsub_rn(1.0f, x0) : 0.0f;
    float a1 = (h1 >= 0 && h1 < in_size) ? __fsub_rn(1.0f, x1) : 0.0f;
    float tot = __fadd_rn(a0, a1);
    w0 = __fdiv_rn(a0, tot);
    w1 = __fdiv_rn(a1, tot);
    i0 = min(in_size - 1, max(0, h0));
    i1 = min(in_size - 1, max(0, h1));
}

__global__ void k_fullspec(const float* __restrict__ params, float* __restrict__ fs) {
    int i = blockIdx.x * blockDim.x + threadIdx.x;
    if (i >= OUT_FS) return;
    int w = i & 511;
    int h = (i >> 9) & 127;
    int b = i >> 16;
    float py = __fsub_rn(__fmul_rn(__fadd_rn((float)h, 0.5f), 0.25f),  0.5f);
    float px = __fsub_rn(__fmul_rn(__fadd_rn((float)w, 0.5f), 0.125f), 0.5f);
    int y0, y1, x0, x1; float wy0, wy1, wx0, wx1;
    lin_weights(py, GH, y0, y1, wy0, wy1);
    lin_weights(px, GW, x0, x1, wx0, wx1);
    const float* g = params + b * (GH*GW);
    float v00 = g[y0*GW + x0], v01 = g[y0*GW + x1];
    float v10 = g[y1*GW + x0], v11 = g[y1*GW + x1];
    float c0 = __fadd_rn(__fmul_rn(wy0, v00), __fmul_rn(wy1, v10));
    float c1 = __fadd_rn(__fmul_rn(wy0, v01), __fmul_rn(wy1, v11));
    fs[i] = __fadd_rn(__fmul_rn(wx0, c0), __fmul_rn(wx1, c1));
}

__global__ void k_mag(const float* __restrict__ fs) {
    int i = blockIdx.x * blockDim.x + threadIdx.x;
    if (i >= NTOT) return;
    int k  = i % NK;
    int bf = i / NK;
    int f  = bf & (NFRAMES - 1);
    int b  = bf >> 9;
    const float invs = (float)(128.0 / 513.0);
    float p = __fsub_rn(__fmul_rn(__fadd_rn((float)k, 0.5f), invs), 0.5f);
    int h0, h1; float w0, w1;
    lin_weights(p, FULL_H, h0, h1, w0, w1);
    const float* fb = fs + (size_t)b * (FULL_H * FULL_W);
    float a0 = fb[h0 * FULL_W + f];
    float a1 = fb[h1 * FULL_W + f];
    float sp0 = __fmul_rn(__fmul_rn(a0, a0), 100.0f);
    float sp1 = __fmul_rn(__fmul_rn(a1, a1), 100.0f);
    float v = __fadd_rn(__fmul_rn(w0, sp0), __fmul_rn(w1, sp1));
    g_mag[i] = sqrtf(fmaxf(v, 0.0f));
}

__global__ void k_init_phase() {
    int i = blockIdx.x * blockDim.x + threadIdx.x;
    if (i >= NTOT) return;
    int k  = i % NK;
    int bf = i / NK;
    int f  = bf & (NFRAMES - 1);
    int b  = bf >> 9;
    unsigned cnt = (unsigned)((b * NK + k) * NFRAMES + f);
    uint2 r = threefry_01(0u, cnt);
    unsigned bits = r.x ^ r.y;
    float u = __uint_as_float((bits >> 9) | 0x3f800000u) - 1.0f;
    float th = __fmul_rn(TWOPI_F, u);
    float sn, cs;
    sincosf(th, &sn, &cs);
    float m = g_mag[i];
    g_S[i] = make_float2(__fmul_rn(m, cs), __fmul_rn(m, sn));
    g_T[i] = make_float2(0.f, 0.f);
}

// ---------------------------------------------------------------------------
// ISTFT (f32): irfft via 512-pt complex IFFT (real packing), * win.
// Exact FFT (iteration 0 feed).
// ---------------------------------------------------------------------------
__global__ void k_istft_frames_f32() {
    int bf  = blockIdx.x;
    int tid = threadIdx.x;
    __shared__ float2 a[512];
    const float2* Sp = g_S + (size_t)bf * NK;
    #pragma unroll
    for (int rep = 0; rep < 2; rep++) {
        int k = tid + rep * 256;
        float2 xk = Sp[k];
        float2 xm = Sp[512 - k];
        float xky = (k == 0) ? 0.0f : xk.y;
        float xmy = (k == 0) ? 0.0f : xm.y;
        float Sx = xk.x + xm.x;
        float Sy = xky - xmy;
        float Dx = xk.x - xm.x;
        float Dy = xky + xmy;
        float2 t = g_twdf1024[k];
        a[brev9(k)] = make_float2(Sx - t.x * Dy + t.y * Dx,
                                  Sy + t.x * Dx + t.y * Dy);
    }
    __syncthreads();
    fft512f(a, tid, true);
    float2* fr = (float2*)(g_frames + (size_t)bf * NFFT);
    #pragma unroll
    for (int rep = 0; rep < 2; rep++) {
        int m = tid + rep * 256;
        float2 ym = a[m];
        float y0 = ym.x * (1.0f / 1024.0f);
        float y1 = ym.y * (1.0f / 1024.0f);
        fr[m] = make_float2(__fmul_rn(y0, g_win[2*m]),
                            __fmul_rn(y1, g_win[2*m + 1]));
    }
}

// ---------------------------------------------------------------------------
// OLA: vectorized interior + scalar boundary (bit-identical to scalar path).
// ---------------------------------------------------------------------------
__global__ void k_ola() {
    int i = blockIdx.x * blockDim.x + threadIdx.x;     // quad index
    if (i >= GB * (LSIG / 4)) return;
    int b  = i / (LSIG / 4);
    int tq = (i - b * (LSIG / 4)) * 4;
    const float* fr = g_frames + (size_t)b * NFRAMES * NFFT;

    if (tq >= 256 && tq <= LSIG - 260) {
        int t   = tq + 512;
        int flo = (t >> 8) - 3;
        int r   = t & 255;
        const float4 a0 = *(const float4*)(fr + (size_t)(flo + 0) * NFFT + (768 + r));
        const float4 a1 = *(const float4*)(fr + (size_t)(flo + 1) * NFFT + (512 + r));
        const float4 a2 = *(const float4*)(fr + (size_t)(flo + 2) * NFFT + (256 + r));
        const float4 a3 = *(const float4*)(fr + (size_t)(flo + 3) * NFFT + r);
        const float4 d4 = *(const float4*)(g_w2tab + r);
        float4 o;
        {
            float s;
            s = __fadd_rn(0.0f, a0.x); s = __fadd_rn(s, a1.x); s = __fadd_rn(s, a2.x); s = __fadd_rn(s, a3.x);
            o.x = __fdiv_rn(s, (d4.x > 1e-11f) ? d4.x : 1.0f);
            s = __fadd_rn(0.0f, a0.y); s = __fadd_rn(s, a1.y); s = __fadd_rn(s, a2.y); s = __fadd_rn(s, a3.y);
            o.y = __fdiv_rn(s, (d4.y > 1e-11f) ? d4.y : 1.0f);
            s = __fadd_rn(0.0f, a0.z); s = __fadd_rn(s, a1.z); s = __fadd_rn(s, a2.z); s = __fadd_rn(s, a3.z);
            o.z = __fdiv_rn(s, (d4.z > 1e-11f) ? d4.z : 1.0f);
            s = __fadd_rn(0.0f, a0.w); s = __fadd_rn(s, a1.w); s = __fadd_rn(s, a2.w); s = __fadd_rn(s, a3.w);
            o.w = __fdiv_rn(s, (d4.w > 1e-11f) ? d4.w : 1.0f);
        }
        *(float4*)(g_audio + (size_t)b * LSIG + tq) = o;
    } else {
        #pragma unroll
        for (int j = 0; j < 4; j++) {
            int tp = tq + j;
            int t  = tp + 512;
            int fhi = min(NFRAMES - 1, t >> 8);
            int flo = max(0, (t - 768) >> 8);
            float s = 0.f, w2 = 0.f;
            for (int f = flo; f <= fhi; f++) {
                int n = t - (f << 8);
                s  = __fadd_rn(s,  fr[(size_t)f * NFFT + n]);
                w2 = __fadd_rn(w2, g_win2[n]);
            }
            float den = (w2 > 1e-11f) ? w2 : 1.0f;
            g_audio[(size_t)b * LSIG + tp] = __fdiv_rn(s, den);
        }
    }
}

// ---------------------------------------------------------------------------
// FUSED (exact, 1 frame / 256 threads): iterations 0..FAST_START-1.
// ---------------------------------------------------------------------------
__global__ void __launch_bounds__(256) k_fused_update_istft() {
    int bf  = blockIdx.x;
    int f   = bf & (NFRAMES - 1);
    int b   = bf >> 9;
    int tid = threadIdx.x;
    __shared__ float2 a[512];
    __shared__ float2 Srow[NK];

    const float* au = g_audio + (size_t)b * LSIG;
    #pragma unroll
    for (int rep = 0; rep < 2; rep++) {
        int m = tid + rep * 256;
        int n0 = 2 * m, n1 = 2 * m + 1;
        int i0 = (f << 8) + n0 - 512;
        int i1 = i0 + 1;
        if (i0 < 0) i0 = -i0; else if (i0 >= LSIG) i0 = 2 * LSIG - 2 - i0;
        if (i1 < 0) i1 = -i1; else if (i1 >= LSIG) i1 = 2 * LSIG - 2 - i1;
        float xv0 = __fmul_rn(au[i0], g_win[n0]);
        float xv1 = __fmul_rn(au[i1], g_win[n1]);
        a[brev9(m)] = make_float2(xv0, xv1);
    }
    __syncthreads();

    fft512f(a, tid, false);

    size_t base = (size_t)bf * NK;
    const float cmom = (float)(0.99 / 1.99);
    for (int k = tid; k < NK; k += 256) {
        int m1 = (512 - k) & 511;
        float2 P = a[k & 511];
        float2 Q = a[m1];
        float Sx = P.x + Q.x, Sy = P.y - Q.y;
        float Dx = P.x - Q.x, Dy = P.y + Q.y;
        float2 t = g_twdf1024[k];
        float Rx = 0.5f * (Sx + t.x * Dy + t.y * Dx);
        float Ry = 0.5f * (Sy - (t.x * Dx - t.y * Dy));
        float2 tp = g_T[base + k];
        float ax = __fsub_rn(Rx, __fmul_rn(cmom, tp.x));
        float ay = __fsub_rn(Ry, __fmul_rn(cmom, tp.y));
        double dm = sqrt((double)ax * (double)ax + (double)ay * (double)ay);
        float d = __fadd_rn((float)dm, 1e-16f);
        float anx = __fdiv_rn(ax, d);
        float any = __fdiv_rn(ay, d);
        float m = g_mag[base + k];
        Srow[k] = make_float2(__fmul_rn(m, anx), __fmul_rn(m, any));
        g_T[base + k] = make_float2(Rx, Ry);
    }
    __syncthreads();

    #pragma unroll
    for (int rep = 0; rep < 2; rep++) {
        int k = tid + rep * 256;
        float2 xk = Srow[k];
        float2 xm = Srow[512 - k];
        float xky = (k == 0) ? 0.0f : xk.y;
        float xmy = (k == 0) ? 0.0f : xm.y;
        float Sx = xk.x + xm.x;
        float Sy = xky - xmy;
        float Dx = xk.x - xm.x;
        float Dy = xky + xmy;
        float2 t = g_twdf1024[k];
        a[brev9(k)] = make_float2(Sx - t.x * Dy + t.y * Dx,
                                  Sy + t.x * Dx + t.y * Dy);
    }
    __syncthreads();

    fft512f(a, tid, true);
    float2* fr = (float2*)(g_frames + (size_t)bf * NFFT);
    #pragma unroll
    for (int rep = 0; rep < 2; rep++) {
        int m = tid + rep * 256;
        float2 ym = a[m];
        float y0 = ym.x * (1.0f / 1024.0f);
        float y1 = ym.y * (1.0f / 1024.0f);
        fr[m] = make_float2(__fmul_rn(y0, g_win[2*m]),
                            __fmul_rn(y1, g_win[2*m + 1]));
    }
}

// ---------------------------------------------------------------------------
// FUSED FAST (4 frames / block, 64 threads per frame group). Per-frame
// arithmetic expressions identical; only the thread->frame mapping changed.
// ---------------------------------------------------------------------------
__global__ void __launch_bounds__(256) k_fused_update_istft_fast() {
    int grp = threadIdx.x >> 6;            // 0..3
    int t   = threadIdx.x & 63;            // 0..63 within group
    int bf  = blockIdx.x * 4 + grp;
    int f   = bf & (NFRAMES - 1);
    int b   = bf >> 9;
    __shared__ float2 aS[4][512];
    __shared__ float2 SrowS[4][NK];
    float2* a    = aS[grp];
    float2* Srow = SrowS[grp];

    // --- load windowed audio frame (reflect pad), bit-reversed placement ---
    const float* au = g_audio + (size_t)b * LSIG;
    #pragma unroll
    for (int rep = 0; rep < 8; rep++) {
        int m = t + rep * 64;
        int n0 = 2 * m, n1 = 2 * m + 1;
        int i0 = (f << 8) + n0 - 512;
        int i1 = i0 + 1;
        if (i0 < 0) i0 = -i0; else if (i0 >= LSIG) i0 = 2 * LSIG - 2 - i0;
        if (i1 < 0) i1 = -i1; else if (i1 >= LSIG) i1 = 2 * LSIG - 2 - i1;
        float xv0 = __fmul_rn(au[i0], g_win[n0]);
        float xv1 = __fmul_rn(au[i1], g_win[n1]);
        a[brev9(m)] = make_float2(xv0, xv1);
    }
    __syncthreads();

    // --- forward FFT ---
    fft512f_fast_grp(a, t, false);

    // --- unpack + GL update ---
    size_t base = (size_t)bf * NK;
    const float cmom = (float)(0.99 / 1.99);
    for (int k = t; k < NK; k += 64) {
        int m1 = (512 - k) & 511;
        float2 P = a[k & 511];
        float2 Q = a[m1];
        float Sx = P.x + Q.x, Sy = P.y - Q.y;
        float Dx = P.x - Q.x, Dy = P.y + Q.y;
        float2 tw = g_twdf1024[k];
        float Rx = 0.5f * (Sx + tw.x * Dy + tw.y * Dx);
        float Ry = 0.5f * (Sy - (tw.x * Dx - tw.y * Dy));
        float2 tp = g_T[base + k];
        float ax = __fsub_rn(Rx, __fmul_rn(cmom, tp.x));
        float ay = __fsub_rn(Ry, __fmul_rn(cmom, tp.y));
        double dm = sqrt((double)ax * (double)ax + (double)ay * (double)ay);
        float d = __fadd_rn((float)dm, 1e-16f);
        float anx = __fdiv_rn(ax, d);
        float any = __fdiv_rn(ay, d);
        float m = g_mag[base + k];
        Srow[k] = make_float2(__fmul_rn(m, anx), __fmul_rn(m, any));
        g_T[base + k] = make_float2(Rx, Ry);
    }
    __syncthreads();

    // --- repack hermitian row, bit-reversed placement ---
    #pragma unroll
    for (int rep = 0; rep < 8; rep++) {
        int k = t + rep * 64;
        float2 xk = Srow[k];
        float2 xm = Srow[512 - k];
        float xky = (k == 0) ? 0.0f : xk.y;
        float xmy = (k == 0) ? 0.0f : xm.y;
        float Sx = xk.x + xm.x;
        float Sy = xky - xmy;
        float Dx = xk.x - xm.x;
        float Dy = xky + xmy;
        float2 tw = g_twdf1024[k];
        a[brev9(k)] = make_float2(Sx - tw.x * Dy + tw.y * Dx,
                                  Sy + tw.x * Dx + tw.y * Dy);
    }
    __syncthreads();

    // --- inverse FFT + window + write frames ---
    fft512f_fast_grp(a, t, true);
    float2* fr = (float2*)(g_frames + (size_t)bf * NFFT);
    #pragma unroll
    for (int rep = 0; rep < 8; rep++) {
        int m = t + rep * 64;
        float2 ym = a[m];
        float y0 = ym.x * (1.0f / 1024.0f);
        float y1 = ym.y * (1.0f / 1024.0f);
        fr[m] = make_float2(__fmul_rn(y0, g_win[2*m]),
                            __fmul_rn(y1, g_win[2*m + 1]));
    }
}

// ---------------------------------------------------------------------------
__global__ void k_max() {
    int b   = blockIdx.x;
    int tid = threadIdx.x;
    __shared__ float red[1024];
    const float* au = g_audio + (size_t)b * LSIG;
    float m = 0.f;
    for (int i = tid; i < LSIG; i += 1024) m = fmaxf(m, fabsf(au[i]));
    red[tid] = m;
    __syncthreads();
    for (int s = 512; s > 0; s >>= 1) {
        if (tid < s) red[tid] = fmaxf(red[tid], red[tid + s]);
        __syncthreads();
    }
    if (tid == 0) g_maxv[b] = fmaxf(red[0], 1e-8f);
}

__global__ void k_final(float* __restrict__ out) {
    int i = blockIdx.x * blockDim.x + threadIdx.x;
    if (i >= OUT_AUDIO) return;
    int b = i >> 17;
    int t = i & (NSAMP - 1);
    float v = 0.f;
    if (t < LSIG)
        v = __fmul_rn(__fdiv_rn(g_audio[(size_t)b * LSIG + t], g_maxv[b]), 0.9f);
    out[i] = v;
}

// ---------------------------------------------------------------------------
extern "C" void kernel_launch(void* const* d_in, const int* in_sizes, int n_in,
                              void* d_out, int out_size) {
    const float* params = (const float*)d_in[0];
    float* out = (float*)d_out;
    float* fs_out = out + OUT_AUDIO;

    k_init_tables<<<4, 256>>>();
    k_init_w2tab<<<1, 256>>>();
    k_fullspec<<<(OUT_FS + 255) / 256, 256>>>(params, fs_out);
    k_mag<<<(NTOT + 255) / 256, 256>>>(fs_out);
    k_init_phase<<<(NTOT + 255) / 256, 256>>>();

    const int NBF = GB * NFRAMES;
    const int OLA_BLOCKS = (GB * (LSIG / 4) + 255) / 256;
    // initial ISTFT from S0 -> frames (exact FFT)
    k_istft_frames_f32<<<NBF, 256>>>();
    // 32 GL iterations: exact FFT early, 4-frame radix-8 register FFT late
    for (int it = 0; it < 32; it++) {
        k_ola<<<OLA_BLOCKS, 256>>>();
        if (it < FAST_START)
            k_fused_update_istft<<<NBF, 256>>>();
        else
            k_fused_update_istft_fast<<<NBF / 4, 256>>>();
    }
    // final OLA, then normalize
    k_ola<<<OLA_BLOCKS, 256>>>();
    k_max<<<GB, 1024>>>();
    k_final<<<(OUT_AUDIO + 255) / 256, 256>>>(out);
}

// round 16
// speedup vs baseline: 1.1293x; 1.1293x over previous
#include <cuda_runtime.h>
#include <math.h>
#include <stdint.h>

#define GB       8
#define GH       32
#define GW       64
#define FULL_H   128
#define FULL_W   512
#define NFFT     1024
#define HOP      256
#define NK       513
#define NFRAMES  512
#define LSIG     130816
#define NSAMP    131072
#define NTOT     (GB*NFRAMES*NK)
#define OUT_AUDIO (GB*NSAMP)
#define OUT_FS    (GB*FULL_H*FULL_W)

#define FAST_START 4    /* GL iterations >= this use the radix-8 register FFT */

#define TWOPI_F  6.28318548202514648438f   /* f32(2*pi) */

// 9-bit bit reversal (pure permutation)
__device__ __forceinline__ int brev9(int i) { return __brev(i) >> 23; }

// ---------------------------------------------------------------------------
// Device scratch
// ---------------------------------------------------------------------------
__device__ float   g_win[NFFT];
__device__ float   g_win2[NFFT];
__device__ float2  g_twdf1024[NK];    // e^{-2pi i k/1024}, f32 (rounded from f64)
__device__ float   g_mag[NTOT];
__device__ float2  g_S[NTOT];         // only used for initial spectrum
__device__ float2  g_T[NTOT];
__device__ float   g_frames[GB*NFRAMES*NFFT];
__device__ float   g_audio[GB*LSIG];
__device__ float   g_maxv[GB];

// ---------------------------------------------------------------------------
__global__ void k_init_tables() {
    int i = blockIdx.x * blockDim.x + threadIdx.x;
    if (i < NFFT) {
        float af = __fdiv_rn(__fmul_rn(TWOPI_F, (float)i), 1024.0f);
        float c  = (float)cos((double)af);
        float w  = __fmul_rn(0.5f, __fsub_rn(1.0f, c));
        g_win[i]  = w;
        g_win2[i] = __fmul_rn(w, w);
    }
    if (i < NK) {
        double a = 2.0 * M_PI * (double)i / 1024.0;
        g_twdf1024[i] = make_float2((float)cos(a), (float)(-sin(a)));
    }
}

// ---------------------------------------------------------------------------
// threefry2x32, key (0,1)
// ---------------------------------------------------------------------------
__device__ __forceinline__ unsigned rotl32(unsigned x, int r) {
    return (x << r) | (x >> (32 - r));
}
__device__ __forceinline__ uint2 threefry_01(unsigned c0, unsigned c1) {
    const unsigned k0 = 0u, k1 = 1u;
    const unsigned k2 = 0x1BD11BDAu ^ k0 ^ k1;
    unsigned x0 = c0 + k0, x1 = c1 + k1;
#define TFR(r) { x0 += x1; x1 = rotl32(x1, (r)); x1 ^= x0; }
    TFR(13) TFR(15) TFR(26) TFR(6)
    x0 += k1; x1 += k2 + 1u;
    TFR(17) TFR(29) TFR(16) TFR(24)
    x0 += k2; x1 += k0 + 2u;
    TFR(13) TFR(15) TFR(26) TFR(6)
    x0 += k0; x1 += k1 + 3u;
    TFR(17) TFR(29) TFR(16) TFR(24)
    x0 += k1; x1 += k2 + 4u;
    TFR(13) TFR(15) TFR(26) TFR(6)
    x0 += k2; x1 += k0 + 5u;
#undef TFR
    return make_uint2(x0, x1);
}

// ---------------------------------------------------------------------------
// EXACT 512-pt complex FFT, f32, 256 threads. Input already bit-reversed.
// This stage-loop body is load-bearing for bit-exactness — DO NOT RESTRUCTURE.
// ---------------------------------------------------------------------------
__device__ __forceinline__ void fft512f(float2* a, int tid, bool inverse) {
    #pragma unroll
    for (int s = 0; s < 9; s++) {
        int half = 1 << s;
        int pos  = tid & (half - 1);
        int i0   = ((tid >> s) << (s + 1)) + pos;
        int i1   = i0 + half;
        float2 t = g_twdf1024[pos << (9 - s)];
        float ty = inverse ? -t.y : t.y;
        float2 u = a[i0], v = a[i1];
        float vr = v.x * t.x - v.y * ty;
        float vi = v.x * ty + v.y * t.x;
        a[i0] = make_float2(u.x + vr, u.y + vi);
        a[i1] = make_float2(u.x - vr, u.y - vi);
        __syncthreads();
    }
}

// ---------------------------------------------------------------------------
// FAST 512-pt FFT: radix-8 register phases (3 stages per smem touch-round).
// 64 threads x 8 elements; idle warps are hidden by inter-block occupancy.
// ---------------------------------------------------------------------------
__device__ __forceinline__ void bfly(float2& u, float2& v, float2 t, bool inverse) {
    float ty = inverse ? -t.y : t.y;
    float vr = v.x * t.x - v.y * ty;
    float vi = v.x * ty + v.y * t.x;
    float2 nu = make_float2(u.x + vr, u.y + vi);
    float2 nv = make_float2(u.x - vr, u.y - vi);
    u = nu; v = nv;
}

template <int S>
__device__ __forceinline__ void radix8_phase(float2* a, int t, bool inverse) {
    const int q = 1 << S;
    int base = ((t >> S) << (S + 3)) + (t & (q - 1));
    float2 x[8];
    #pragma unroll
    for (int j = 0; j < 8; j++) x[j] = a[base + j * q];
    #pragma unroll
    for (int k = 0; k < 3; k++) {
        int step = 1 << k;
        #pragma unroll
        for (int j = 0; j < 8; j++) {
            if ((j & step) == 0) {
                int pos = (t & (q - 1)) + q * (j & (step - 1));
                float2 tw = g_twdf1024[pos << (9 - S - k)];
                bfly(x[j], x[j + step], tw, inverse);
            }
        }
    }
    #pragma unroll
    for (int j = 0; j < 8; j++) a[base + j * q] = x[j];
}

__device__ __forceinline__ void fft512f_fast(float2* a, int tid, bool inverse) {
    if (tid < 64) {
        radix8_phase<0>(a, tid, inverse);
        __syncwarp();
        radix8_phase<3>(a, tid, inverse);
    }
    __syncthreads();
    if (tid < 64) {
        radix8_phase<6>(a, tid, inverse);
    }
    __syncthreads();
}

// ---------------------------------------------------------------------------
// Bilinear tap weights (compute_weight_mat f32 mimicry)
// ---------------------------------------------------------------------------
__device__ __forceinline__ void lin_weights(float p, int in_size,
                                            int& i0, int& i1,
                                            float& w0, float& w1) {
    int h0 = (int)floorf(p);
    int h1 = h0 + 1;
    float x0 = __fsub_rn(p, (float)h0);
    float x1 = __fsub_rn((float)h1, p);
    float a0 = (h0 >= 0 && h0 < in_size) ? __fsub_rn(1.0f, x0) : 0.0f;
    float a1 = (h1 >= 0 && h1 < in_size) ? __fsub_rn(1.0f, x1) : 0.0f;
    float tot = __fadd_rn(a0, a1);
    w0 = __fdiv_rn(a0, tot);
    w1 = __fdiv_rn(a1, tot);
    i0 = min(in_size - 1, max(0, h0));
    i1 = min(in_size - 1, max(0, h1));
}

__global__ void k_fullspec(const float* __restrict__ params, float* __restrict__ fs) {
    int i = blockIdx.x * blockDim.x + threadIdx.x;
    if (i >= OUT_FS) return;
    int w = i & 511;
    int h = (i >> 9) & 127;
    int b = i >> 16;
    float py = __fsub_rn(__fmul_rn(__fadd_rn((float)h, 0.5f), 0.25f),  0.5f);
    float px = __fsub_rn(__fmul_rn(__fadd_rn((float)w, 0.5f), 0.125f), 0.5f);
    int y0, y1, x0, x1; float wy0, wy1, wx0, wx1;
    lin_weights(py, GH, y0, y1, wy0, wy1);
    lin_weights(px, GW, x0, x1, wx0, wx1);
    const float* g = params + b * (GH*GW);
    float v00 = g[y0*GW + x0], v01 = g[y0*GW + x1];
    float v10 = g[y1*GW + x0], v11 = g[y1*GW + x1];
    float c0 = __fadd_rn(__fmul_rn(wy0, v00), __fmul_rn(wy1, v10));
    float c1 = __fadd_rn(__fmul_rn(wy0, v01), __fmul_rn(wy1, v11));
    fs[i] = __fadd_rn(__fmul_rn(wx0, c0), __fmul_rn(wx1, c1));
}

__global__ void k_mag(const float* __restrict__ fs) {
    int i = blockIdx.x * blockDim.x + threadIdx.x;
    if (i >= NTOT) return;
    int k  = i % NK;
    int bf = i / NK;
    int f  = bf & (NFRAMES - 1);
    int b  = bf >> 9;
    const float invs = (float)(128.0 / 513.0);
    float p = __fsub_rn(__fmul_rn(__fadd_rn((float)k, 0.5f), invs), 0.5f);
    int h0, h1; float w0, w1;
    lin_weights(p, FULL_H, h0, h1, w0, w1);
    const float* fb = fs + (size_t)b * (FULL_H * FULL_W);
    float a0 = fb[h0 * FULL_W + f];
    float a1 = fb[h1 * FULL_W + f];
    float sp0 = __fmul_rn(__fmul_rn(a0, a0), 100.0f);
    float sp1 = __fmul_rn(__fmul_rn(a1, a1), 100.0f);
    float v = __fadd_rn(__fmul_rn(w0, sp0), __fmul_rn(w1, sp1));
    g_mag[i] = sqrtf(fmaxf(v, 0.0f));
}

__global__ void k_init_phase() {
    int i = blockIdx.x * blockDim.x + threadIdx.x;
    if (i >= NTOT) return;
    int k  = i % NK;
    int bf = i / NK;
    int f  = bf & (NFRAMES - 1);
    int b  = bf >> 9;
    unsigned cnt = (unsigned)((b * NK + k) * NFRAMES + f);
    uint2 r = threefry_01(0u, cnt);
    unsigned bits = r.x ^ r.y;
    float u = __uint_as_float((bits >> 9) | 0x3f800000u) - 1.0f;
    float th = __fmul_rn(TWOPI_F, u);
    float sn, cs;
    sincosf(th, &sn, &cs);
    float m = g_mag[i];
    g_S[i] = make_float2(__fmul_rn(m, cs), __fmul_rn(m, sn));
    g_T[i] = make_float2(0.f, 0.f);
}

// ---------------------------------------------------------------------------
// ISTFT (f32): irfft via 512-pt complex IFFT (real packing), * win.
// Pack writes directly in bit-reversed order. Exact FFT (iteration 0 feed).
// ---------------------------------------------------------------------------
__global__ void k_istft_frames_f32() {
    int bf  = blockIdx.x;
    int tid = threadIdx.x;
    __shared__ float2 a[512];
    const float2* Sp = g_S + (size_t)bf * NK;
    #pragma unroll
    for (int rep = 0; rep < 2; rep++) {
        int k = tid + rep * 256;
        float2 xk = Sp[k];
        float2 xm = Sp[512 - k];
        float xky = (k == 0) ? 0.0f : xk.y;
        float xmy = (k == 0) ? 0.0f : xm.y;
        float Sx = xk.x + xm.x;
        float Sy = xky - xmy;
        float Dx = xk.x - xm.x;
        float Dy = xky + xmy;
        float2 t = g_twdf1024[k];
        a[brev9(k)] = make_float2(Sx - t.x * Dy + t.y * Dx,
                                  Sy + t.x * Dx + t.y * Dy);
    }
    __syncthreads();
    fft512f(a, tid, true);
    float2* fr = (float2*)(g_frames + (size_t)bf * NFFT);
    #pragma unroll
    for (int rep = 0; rep < 2; rep++) {
        int m = tid + rep * 256;
        float2 ym = a[m];
        float y0 = ym.x * (1.0f / 1024.0f);
        float y1 = ym.y * (1.0f / 1024.0f);
        fr[m] = make_float2(__fmul_rn(y0, g_win[2*m]),
                            __fmul_rn(y1, g_win[2*m + 1]));
    }
}

// ---------------------------------------------------------------------------
// OLA (scalar, R13-proven)
// ---------------------------------------------------------------------------
__global__ void k_ola() {
    int i = blockIdx.x * blockDim.x + threadIdx.x;
    if (i >= GB * LSIG) return;
    int b  = i / LSIG;
    int tp = i - b * LSIG;
    int t  = tp + 512;
    int fhi = min(NFRAMES - 1, t >> 8);
    int flo = max(0, (t - 768) >> 8);
    const float* fr = g_frames + (size_t)b * NFRAMES * NFFT;
    float s = 0.f, w2 = 0.f;
    for (int f = flo; f <= fhi; f++) {
        int n = t - (f << 8);
        s  = __fadd_rn(s,  fr[(size_t)f * NFFT + n]);
        w2 = __fadd_rn(w2, g_win2[n]);
    }
    float den = (w2 > 1e-11f) ? w2 : 1.0f;
    g_audio[i] = __fdiv_rn(s, den);
}

// ---------------------------------------------------------------------------
// FUSED kernel body: forward STFT + GL update + inverse ISTFT.
// ---------------------------------------------------------------------------
template <bool FAST>
__device__ __forceinline__ void fused_body() {
    int bf  = blockIdx.x;
    int f   = bf & (NFRAMES - 1);
    int b   = bf >> 9;
    int tid = threadIdx.x;
    __shared__ float2 a[512];
    __shared__ float2 Srow[NK];

    // --- load windowed audio frame (reflect pad), bit-reversed placement ---
    const float* au = g_audio + (size_t)b * LSIG;
    #pragma unroll
    for (int rep = 0; rep < 2; rep++) {
        int m = tid + rep * 256;
        int n0 = 2 * m, n1 = 2 * m + 1;
        int i0 = (f << 8) + n0 - 512;
        int i1 = i0 + 1;
        if (i0 < 0) i0 = -i0; else if (i0 >= LSIG) i0 = 2 * LSIG - 2 - i0;
        if (i1 < 0) i1 = -i1; else if (i1 >= LSIG) i1 = 2 * LSIG - 2 - i1;
        float xv0 = __fmul_rn(au[i0], g_win[n0]);
        float xv1 = __fmul_rn(au[i1], g_win[n1]);
        a[brev9(m)] = make_float2(xv0, xv1);
    }
    __syncthreads();

    // --- forward FFT (real packing) ---
    if (FAST) fft512f_fast(a, tid, false); else fft512f(a, tid, false);

    // --- unpack + GL update; new S row into smem ---
    size_t base = (size_t)bf * NK;
    const float cmom = (float)(0.99 / 1.99);
    for (int k = tid; k < NK; k += 256) {
        int m1 = (512 - k) & 511;
        float2 P = a[k & 511];
        float2 Q = a[m1];
        float Sx = P.x + Q.x, Sy = P.y - Q.y;
        float Dx = P.x - Q.x, Dy = P.y + Q.y;
        float2 t = g_twdf1024[k];
        float Rx = 0.5f * (Sx + t.x * Dy + t.y * Dx);
        float Ry = 0.5f * (Sy - (t.x * Dx - t.y * Dy));
        float2 tp = g_T[base + k];
        float ax = __fsub_rn(Rx, __fmul_rn(cmom, tp.x));
        float ay = __fsub_rn(Ry, __fmul_rn(cmom, tp.y));
        double dm = sqrt((double)ax * (double)ax + (double)ay * (double)ay);
        float d = __fadd_rn((float)dm, 1e-16f);
        float anx = __fdiv_rn(ax, d);
        float any = __fdiv_rn(ay, d);
        float m = g_mag[base + k];
        Srow[k] = make_float2(__fmul_rn(m, anx), __fmul_rn(m, any));
        g_T[base + k] = make_float2(Rx, Ry);
    }
    __syncthreads();

    // --- repack hermitian row for inverse FFT, bit-reversed placement ---
    #pragma unroll
    for (int rep = 0; rep < 2; rep++) {
        int k = tid + rep * 256;
        float2 xk = Srow[k];
        float2 xm = Srow[512 - k];
        float xky = (k == 0) ? 0.0f : xk.y;
        float xmy = (k == 0) ? 0.0f : xm.y;
        float Sx = xk.x + xm.x;
        float Sy = xky - xmy;
        float Dx = xk.x - xm.x;
        float Dy = xky + xmy;
        float2 t = g_twdf1024[k];
        a[brev9(k)] = make_float2(Sx - t.x * Dy + t.y * Dx,
                                  Sy + t.x * Dx + t.y * Dy);
    }
    __syncthreads();

    // --- inverse FFT + window + write frames ---
    if (FAST) fft512f_fast(a, tid, true); else fft512f(a, tid, true);
    float2* fr = (float2*)(g_frames + (size_t)bf * NFFT);
    #pragma unroll
    for (int rep = 0; rep < 2; rep++) {
        int m = tid + rep * 256;
        float2 ym = a[m];
        float y0 = ym.x * (1.0f / 1024.0f);
        float y1 = ym.y * (1.0f / 1024.0f);
        fr[m] = make_float2(__fmul_rn(y0, g_win[2*m]),
                            __fmul_rn(y1, g_win[2*m + 1]));
    }
}

__global__ void __launch_bounds__(256, 8) k_fused_update_istft()      { fused_body<false>(); }
__global__ void __launch_bounds__(256, 8) k_fused_update_istft_fast() { fused_body<true>();  }

// ---------------------------------------------------------------------------
__global__ void k_max() {
    int b   = blockIdx.x;
    int tid = threadIdx.x;
    __shared__ float red[1024];
    const float* au = g_audio + (size_t)b * LSIG;
    float m = 0.f;
    for (int i = tid; i < LSIG; i += 1024) m = fmaxf(m, fabsf(au[i]));
    red[tid] = m;
    __syncthreads();
    for (int s = 512; s > 0; s >>= 1) {
        if (tid < s) red[tid] = fmaxf(red[tid], red[tid + s]);
        __syncthreads();
    }
    if (tid == 0) g_maxv[b] = fmaxf(red[0], 1e-8f);
}

__global__ void k_final(float* __restrict__ out) {
    int i = blockIdx.x * blockDim.x + threadIdx.x;
    if (i >= OUT_AUDIO) return;
    int b = i >> 17;
    int t = i & (NSAMP - 1);
    float v = 0.f;
    if (t < LSIG)
        v = __fmul_rn(__fdiv_rn(g_audio[(size_t)b * LSIG + t], g_maxv[b]), 0.9f);
    out[i] = v;
}

// ---------------------------------------------------------------------------
extern "C" void kernel_launch(void* const* d_in, const int* in_sizes, int n_in,
                              void* d_out, int out_size) {
    const float* params = (const float*)d_in[0];
    float* out = (float*)d_out;
    float* fs_out = out + OUT_AUDIO;

    k_init_tables<<<4, 256>>>();
    k_fullspec<<<(OUT_FS + 255) / 256, 256>>>(params, fs_out);
    k_mag<<<(NTOT + 255) / 256, 256>>>(fs_out);
    k_init_phase<<<(NTOT + 255) / 256, 256>>>();

    const int NBF = GB * NFRAMES;
    // initial ISTFT from S0 -> frames (exact FFT)
    k_istft_frames_f32<<<NBF, 256>>>();
    // 32 GL iterations: exact FFT early (high noise amplification),
    // radix-8 register FFT from iter 4 (drift measured exactly zero there)
    for (int it = 0; it < 32; it++) {
        k_ola<<<(GB * LSIG + 255) / 256, 256>>>();
        if (it < FAST_START)
            k_fused_update_istft<<<NBF, 256>>>();
        else
            k_fused_update_istft_fast<<<NBF, 256>>>();
    }
    // final OLA, then normalize
    k_ola<<<(GB * LSIG + 255) / 256, 256>>>();
    k_max<<<GB, 1024>>>();
    k_final<<<(OUT_AUDIO + 255) / 256, 256>>>(out);
}

// round 17
// speedup vs baseline: 1.1733x; 1.0389x over previous
#include <cuda_runtime.h>
#include <math.h>
#include <stdint.h>

#define GB       8
#define GH       32
#define GW       64
#define FULL_H   128
#define FULL_W   512
#define NFFT     1024
#define HOP      256
#define NK       513
#define NFRAMES  512
#define LSIG     130816
#define NSAMP    131072
#define NTOT     (GB*NFRAMES*NK)
#define OUT_AUDIO (GB*NSAMP)
#define OUT_FS    (GB*FULL_H*FULL_W)

#define FAST_START 4    /* GL iterations >= this use the radix-8 register FFT */

#define TWOPI_F  6.28318548202514648438f   /* f32(2*pi) */

// 9-bit bit reversal (pure permutation)
__device__ __forceinline__ int brev9(int i) { return __brev(i) >> 23; }

// Skewed SoA index: conflict-free banks for radix-8 phases (gcd(9,32)=1)
#define AIDX(i) ((i) + ((i) >> 3))    /* 0..511 -> 0..574 */
#define ASZ 576

// ---------------------------------------------------------------------------
// Device scratch
// ---------------------------------------------------------------------------
__device__ float   g_win[NFFT];
__device__ float   g_win2[NFFT];
__device__ float2  g_twdf1024[NK];    // e^{-2pi i k/1024}, f32 (rounded from f64)
__device__ float   g_mag[NTOT];
__device__ float2  g_S[NTOT];         // only used for initial spectrum
__device__ float2  g_T[NTOT];
__device__ float   g_frames[GB*NFRAMES*NFFT];
__device__ float   g_audio[GB*LSIG];
__device__ float   g_maxv[GB];

// ---------------------------------------------------------------------------
__global__ void k_init_tables() {
    int i = blockIdx.x * blockDim.x + threadIdx.x;
    if (i < NFFT) {
        float af = __fdiv_rn(__fmul_rn(TWOPI_F, (float)i), 1024.0f);
        float c  = (float)cos((double)af);
        float w  = __fmul_rn(0.5f, __fsub_rn(1.0f, c));
        g_win[i]  = w;
        g_win2[i] = __fmul_rn(w, w);
    }
    if (i < NK) {
        double a = 2.0 * M_PI * (double)i / 1024.0;
        g_twdf1024[i] = make_float2((float)cos(a), (float)(-sin(a)));
    }
}

// ---------------------------------------------------------------------------
// threefry2x32, key (0,1)
// ---------------------------------------------------------------------------
__device__ __forceinline__ unsigned rotl32(unsigned x, int r) {
    return (x << r) | (x >> (32 - r));
}
__device__ __forceinline__ uint2 threefry_01(unsigned c0, unsigned c1) {
    const unsigned k0 = 0u, k1 = 1u;
    const unsigned k2 = 0x1BD11BDAu ^ k0 ^ k1;
    unsigned x0 = c0 + k0, x1 = c1 + k1;
#define TFR(r) { x0 += x1; x1 = rotl32(x1, (r)); x1 ^= x0; }
    TFR(13) TFR(15) TFR(26) TFR(6)
    x0 += k1; x1 += k2 + 1u;
    TFR(17) TFR(29) TFR(16) TFR(24)
    x0 += k2; x1 += k0 + 2u;
    TFR(13) TFR(15) TFR(26) TFR(6)
    x0 += k0; x1 += k1 + 3u;
    TFR(17) TFR(29) TFR(16) TFR(24)
    x0 += k1; x1 += k2 + 4u;
    TFR(13) TFR(15) TFR(26) TFR(6)
    x0 += k2; x1 += k0 + 5u;
#undef TFR
    return make_uint2(x0, x1);
}

// ---------------------------------------------------------------------------
// EXACT 512-pt complex FFT, f32, 256 threads. Input already bit-reversed.
// This stage-loop body is load-bearing for bit-exactness — DO NOT RESTRUCTURE.
// ---------------------------------------------------------------------------
__device__ __forceinline__ void fft512f(float2* a, int tid, bool inverse) {
    #pragma unroll
    for (int s = 0; s < 9; s++) {
        int half = 1 << s;
        int pos  = tid & (half - 1);
        int i0   = ((tid >> s) << (s + 1)) + pos;
        int i1   = i0 + half;
        float2 t = g_twdf1024[pos << (9 - s)];
        float ty = inverse ? -t.y : t.y;
        float2 u = a[i0], v = a[i1];
        float vr = v.x * t.x - v.y * ty;
        float vi = v.x * ty + v.y * t.x;
        a[i0] = make_float2(u.x + vr, u.y + vi);
        a[i1] = make_float2(u.x - vr, u.y - vi);
        __syncthreads();
    }
}

// ---------------------------------------------------------------------------
// FAST 512-pt FFT: radix-8 register phases on a skewed SoA smem layout
// (bank-conflict-free). Arithmetic expressions identical to R13/R16.
// ---------------------------------------------------------------------------
__device__ __forceinline__ void bfly(float2& u, float2& v, float2 t, bool inverse) {
    float ty = inverse ? -t.y : t.y;
    float vr = v.x * t.x - v.y * ty;
    float vi = v.x * ty + v.y * t.x;
    float2 nu = make_float2(u.x + vr, u.y + vi);
    float2 nv = make_float2(u.x - vr, u.y - vi);
    u = nu; v = nv;
}

template <int S>
__device__ __forceinline__ void radix8_phase_soa(float* ar, float* ai, int t, bool inverse) {
    const int q = 1 << S;
    int base = ((t >> S) << (S + 3)) + (t & (q - 1));
    float2 x[8];
    #pragma unroll
    for (int j = 0; j < 8; j++) {
        int idx = AIDX(base + j * q);
        x[j] = make_float2(ar[idx], ai[idx]);
    }
    #pragma unroll
    for (int k = 0; k < 3; k++) {
        int step = 1 << k;
        #pragma unroll
        for (int j = 0; j < 8; j++) {
            if ((j & step) == 0) {
                int pos = (t & (q - 1)) + q * (j & (step - 1));
                float2 tw = g_twdf1024[pos << (9 - S - k)];
                bfly(x[j], x[j + step], tw, inverse);
            }
        }
    }
    #pragma unroll
    for (int j = 0; j < 8; j++) {
        int idx = AIDX(base + j * q);
        ar[idx] = x[j].x; ai[idx] = x[j].y;
    }
}

__device__ __forceinline__ void fft512f_fast_soa(float* ar, float* ai, int tid, bool inverse) {
    if (tid < 64) {
        radix8_phase_soa<0>(ar, ai, tid, inverse);
        __syncwarp();
        radix8_phase_soa<3>(ar, ai, tid, inverse);
    }
    __syncthreads();
    if (tid < 64) {
        radix8_phase_soa<6>(ar, ai, tid, inverse);
    }
    __syncthreads();
}

// ---------------------------------------------------------------------------
// Bilinear tap weights (compute_weight_mat f32 mimicry)
// ---------------------------------------------------------------------------
__device__ __forceinline__ void lin_weights(float p, int in_size,
                                            int& i0, int& i1,
                                            float& w0, float& w1) {
    int h0 = (int)floorf(p);
    int h1 = h0 + 1;
    float x0 = __fsub_rn(p, (float)h0);
    float x1 = __fsub_rn((float)h1, p);
    float a0 = (h0 >= 0 && h0 < in_size) ? __fsub_rn(1.0f, x0) : 0.0f;
    float a1 = (h1 >= 0 && h1 < in_size) ? __fsub_rn(1.0f, x1) : 0.0f;
    float tot = __fadd_rn(a0, a1);
    w0 = __fdiv_rn(a0, tot);
    w1 = __fdiv_rn(a1, tot);
    i0 = min(in_size - 1, max(0, h0));
    i1 = min(in_size - 1, max(0, h1));
}

__global__ void k_fullspec(const float* __restrict__ params, float* __restrict__ fs) {
    int i = blockIdx.x * blockDim.x + threadIdx.x;
    if (i >= OUT_FS) return;
    int w = i & 511;
    int h = (i >> 9) & 127;
    int b = i >> 16;
    float py = __fsub_rn(__fmul_rn(__fadd_rn((float)h, 0.5f), 0.25f),  0.5f);
    float px = __fsub_rn(__fmul_rn(__fadd_rn((float)w, 0.5f), 0.125f), 0.5f);
    int y0, y1, x0, x1; float wy0, wy1, wx0, wx1;
    lin_weights(py, GH, y0, y1, wy0, wy1);
    lin_weights(px, GW, x0, x1, wx0, wx1);
    const float* g = params + b * (GH*GW);
    float v00 = g[y0*GW + x0], v01 = g[y0*GW + x1];
    float v10 = g[y1*GW + x0], v11 = g[y1*GW + x1];
    float c0 = __fadd_rn(__fmul_rn(wy0, v00), __fmul_rn(wy1, v10));
    float c1 = __fadd_rn(__fmul_rn(wy0, v01), __fmul_rn(wy1, v11));
    fs[i] = __fadd_rn(__fmul_rn(wx0, c0), __fmul_rn(wx1, c1));
}

__global__ void k_mag(const float* __restrict__ fs) {
    int i = blockIdx.x * blockDim.x + threadIdx.x;
    if (i >= NTOT) return;
    int k  = i % NK;
    int bf = i / NK;
    int f  = bf & (NFRAMES - 1);
    int b  = bf >> 9;
    const float invs = (float)(128.0 / 513.0);
    float p = __fsub_rn(__fmul_rn(__fadd_rn((float)k, 0.5f), invs), 0.5f);
    int h0, h1; float w0, w1;
    lin_weights(p, FULL_H, h0, h1, w0, w1);
    const float* fb = fs + (size_t)b * (FULL_H * FULL_W);
    float a0 = fb[h0 * FULL_W + f];
    float a1 = fb[h1 * FULL_W + f];
    float sp0 = __fmul_rn(__fmul_rn(a0, a0), 100.0f);
    float sp1 = __fmul_rn(__fmul_rn(a1, a1), 100.0f);
    float v = __fadd_rn(__fmul_rn(w0, sp0), __fmul_rn(w1, sp1));
    g_mag[i] = sqrtf(fmaxf(v, 0.0f));
}

__global__ void k_init_phase() {
    int i = blockIdx.x * blockDim.x + threadIdx.x;
    if (i >= NTOT) return;
    int k  = i % NK;
    int bf = i / NK;
    int f  = bf & (NFRAMES - 1);
    int b  = bf >> 9;
    unsigned cnt = (unsigned)((b * NK + k) * NFRAMES + f);
    uint2 r = threefry_01(0u, cnt);
    unsigned bits = r.x ^ r.y;
    float u = __uint_as_float((bits >> 9) | 0x3f800000u) - 1.0f;
    float th = __fmul_rn(TWOPI_F, u);
    float sn, cs;
    sincosf(th, &sn, &cs);
    float m = g_mag[i];
    g_S[i] = make_float2(__fmul_rn(m, cs), __fmul_rn(m, sn));
    g_T[i] = make_float2(0.f, 0.f);
}

// ---------------------------------------------------------------------------
// ISTFT (f32): exact FFT (iteration 0 feed). Byte-identical to R16.
// ---------------------------------------------------------------------------
__global__ void k_istft_frames_f32() {
    int bf  = blockIdx.x;
    int tid = threadIdx.x;
    __shared__ float2 a[512];
    const float2* Sp = g_S + (size_t)bf * NK;
    #pragma unroll
    for (int rep = 0; rep < 2; rep++) {
        int k = tid + rep * 256;
        float2 xk = Sp[k];
        float2 xm = Sp[512 - k];
        float xky = (k == 0) ? 0.0f : xk.y;
        float xmy = (k == 0) ? 0.0f : xm.y;
        float Sx = xk.x + xm.x;
        float Sy = xky - xmy;
        float Dx = xk.x - xm.x;
        float Dy = xky + xmy;
        float2 t = g_twdf1024[k];
        a[brev9(k)] = make_float2(Sx - t.x * Dy + t.y * Dx,
                                  Sy + t.x * Dx + t.y * Dy);
    }
    __syncthreads();
    fft512f(a, tid, true);
    float2* fr = (float2*)(g_frames + (size_t)bf * NFFT);
    #pragma unroll
    for (int rep = 0; rep < 2; rep++) {
        int m = tid + rep * 256;
        float2 ym = a[m];
        float y0 = ym.x * (1.0f / 1024.0f);
        float y1 = ym.y * (1.0f / 1024.0f);
        fr[m] = make_float2(__fmul_rn(y0, g_win[2*m]),
                            __fmul_rn(y1, g_win[2*m + 1]));
    }
}

// ---------------------------------------------------------------------------
// OLA (scalar, R13-proven)
// ---------------------------------------------------------------------------
__global__ void k_ola() {
    int i = blockIdx.x * blockDim.x + threadIdx.x;
    if (i >= GB * LSIG) return;
    int b  = i / LSIG;
    int tp = i - b * LSIG;
    int t  = tp + 512;
    int fhi = min(NFRAMES - 1, t >> 8);
    int flo = max(0, (t - 768) >> 8);
    const float* fr = g_frames + (size_t)b * NFRAMES * NFFT;
    float s = 0.f, w2 = 0.f;
    for (int f = flo; f <= fhi; f++) {
        int n = t - (f << 8);
        s  = __fadd_rn(s,  fr[(size_t)f * NFFT + n]);
        w2 = __fadd_rn(w2, g_win2[n]);
    }
    float den = (w2 > 1e-11f) ? w2 : 1.0f;
    g_audio[i] = __fdiv_rn(s, den);
}

// ---------------------------------------------------------------------------
// FUSED EXACT (iterations 0..FAST_START-1): byte-identical to R16.
// ---------------------------------------------------------------------------
__global__ void __launch_bounds__(256, 8) k_fused_update_istft() {
    int bf  = blockIdx.x;
    int f   = bf & (NFRAMES - 1);
    int b   = bf >> 9;
    int tid = threadIdx.x;
    __shared__ float2 a[512];
    __shared__ float2 Srow[NK];

    const float* au = g_audio + (size_t)b * LSIG;
    #pragma unroll
    for (int rep = 0; rep < 2; rep++) {
        int m = tid + rep * 256;
        int n0 = 2 * m, n1 = 2 * m + 1;
        int i0 = (f << 8) + n0 - 512;
        int i1 = i0 + 1;
        if (i0 < 0) i0 = -i0; else if (i0 >= LSIG) i0 = 2 * LSIG - 2 - i0;
        if (i1 < 0) i1 = -i1; else if (i1 >= LSIG) i1 = 2 * LSIG - 2 - i1;
        float xv0 = __fmul_rn(au[i0], g_win[n0]);
        float xv1 = __fmul_rn(au[i1], g_win[n1]);
        a[brev9(m)] = make_float2(xv0, xv1);
    }
    __syncthreads();

    fft512f(a, tid, false);

    size_t base = (size_t)bf * NK;
    const float cmom = (float)(0.99 / 1.99);
    for (int k = tid; k < NK; k += 256) {
        int m1 = (512 - k) & 511;
        float2 P = a[k & 511];
        float2 Q = a[m1];
        float Sx = P.x + Q.x, Sy = P.y - Q.y;
        float Dx = P.x - Q.x, Dy = P.y + Q.y;
        float2 t = g_twdf1024[k];
        float Rx = 0.5f * (Sx + t.x * Dy + t.y * Dx);
        float Ry = 0.5f * (Sy - (t.x * Dx - t.y * Dy));
        float2 tp = g_T[base + k];
        float ax = __fsub_rn(Rx, __fmul_rn(cmom, tp.x));
        float ay = __fsub_rn(Ry, __fmul_rn(cmom, tp.y));
        double dm = sqrt((double)ax * (double)ax + (double)ay * (double)ay);
        float d = __fadd_rn((float)dm, 1e-16f);
        float anx = __fdiv_rn(ax, d);
        float any = __fdiv_rn(ay, d);
        float m = g_mag[base + k];
        Srow[k] = make_float2(__fmul_rn(m, anx), __fmul_rn(m, any));
        g_T[base + k] = make_float2(Rx, Ry);
    }
    __syncthreads();

    #pragma unroll
    for (int rep = 0; rep < 2; rep++) {
        int k = tid + rep * 256;
        float2 xk = Srow[k];
        float2 xm = Srow[512 - k];
        float xky = (k == 0) ? 0.0f : xk.y;
        float xmy = (k == 0) ? 0.0f : xm.y;
        float Sx = xk.x + xm.x;
        float Sy = xky - xmy;
        float Dx = xk.x - xm.x;
        float Dy = xky + xmy;
        float2 t = g_twdf1024[k];
        a[brev9(k)] = make_float2(Sx - t.x * Dy + t.y * Dx,
                                  Sy + t.x * Dx + t.y * Dy);
    }
    __syncthreads();

    fft512f(a, tid, true);
    float2* fr = (float2*)(g_frames + (size_t)bf * NFFT);
    #pragma unroll
    for (int rep = 0; rep < 2; rep++) {
        int m = tid + rep * 256;
        float2 ym = a[m];
        float y0 = ym.x * (1.0f / 1024.0f);
        float y1 = ym.y * (1.0f / 1024.0f);
        fr[m] = make_float2(__fmul_rn(y0, g_win[2*m]),
                            __fmul_rn(y1, g_win[2*m + 1]));
    }
}

// ---------------------------------------------------------------------------
// FUSED FAST (iterations >= FAST_START): skewed SoA smem layout for the FFT
// array. Same arithmetic expressions; placement/addressing only.
// ---------------------------------------------------------------------------
__global__ void __launch_bounds__(256, 8) k_fused_update_istft_fast() {
    int bf  = blockIdx.x;
    int f   = bf & (NFRAMES - 1);
    int b   = bf >> 9;
    int tid = threadIdx.x;
    __shared__ float ar[ASZ];
    __shared__ float ai[ASZ];
    __shared__ float2 Srow[NK];

    // --- load windowed audio frame (reflect pad), bit-reversed placement ---
    const float* au = g_audio + (size_t)b * LSIG;
    #pragma unroll
    for (int rep = 0; rep < 2; rep++) {
        int m = tid + rep * 256;
        int n0 = 2 * m, n1 = 2 * m + 1;
        int i0 = (f << 8) + n0 - 512;
        int i1 = i0 + 1;
        if (i0 < 0) i0 = -i0; else if (i0 >= LSIG) i0 = 2 * LSIG - 2 - i0;
        if (i1 < 0) i1 = -i1; else if (i1 >= LSIG) i1 = 2 * LSIG - 2 - i1;
        float xv0 = __fmul_rn(au[i0], g_win[n0]);
        float xv1 = __fmul_rn(au[i1], g_win[n1]);
        int idx = AIDX(brev9(m));
        ar[idx] = xv0; ai[idx] = xv1;
    }
    __syncthreads();

    // --- forward FFT ---
    fft512f_fast_soa(ar, ai, tid, false);

    // --- unpack + GL update; new S row into smem ---
    size_t base = (size_t)bf * NK;
    const float cmom = (float)(0.99 / 1.99);
    for (int k = tid; k < NK; k += 256) {
        int m1 = (512 - k) & 511;
        int ip = AIDX(k & 511);
        int iq = AIDX(m1);
        float2 P = make_float2(ar[ip], ai[ip]);
        float2 Q = make_float2(ar[iq], ai[iq]);
        float Sx = P.x + Q.x, Sy = P.y - Q.y;
        float Dx = P.x - Q.x, Dy = P.y + Q.y;
        float2 t = g_twdf1024[k];
        float Rx = 0.5f * (Sx + t.x * Dy + t.y * Dx);
        float Ry = 0.5f * (Sy - (t.x * Dx - t.y * Dy));
        float2 tp = g_T[base + k];
        float ax = __fsub_rn(Rx, __fmul_rn(cmom, tp.x));
        float ay = __fsub_rn(Ry, __fmul_rn(cmom, tp.y));
        double dm = sqrt((double)ax * (double)ax + (double)ay * (double)ay);
        float d = __fadd_rn((float)dm, 1e-16f);
        float anx = __fdiv_rn(ax, d);
        float any = __fdiv_rn(ay, d);
        float m = g_mag[base + k];
        Srow[k] = make_float2(__fmul_rn(m, anx), __fmul_rn(m, any));
        g_T[base + k] = make_float2(Rx, Ry);
    }
    __syncthreads();

    // --- repack hermitian row for inverse FFT, bit-reversed placement ---
    #pragma unroll
    for (int rep = 0; rep < 2; rep++) {
        int k = tid + rep * 256;
        float2 xk = Srow[k];
        float2 xm = Srow[512 - k];
        float xky = (k == 0) ? 0.0f : xk.y;
        float xmy = (k == 0) ? 0.0f : xm.y;
        float Sx = xk.x + xm.x;
        float Sy = xky - xmy;
        float Dx = xk.x - xm.x;
        float Dy = xky + xmy;
        float2 t = g_twdf1024[k];
        int idx = AIDX(brev9(k));
        ar[idx] = Sx - t.x * Dy + t.y * Dx;
        ai[idx] = Sy + t.x * Dx + t.y * Dy;
    }
    __syncthreads();

    // --- inverse FFT + window + write frames ---
    fft512f_fast_soa(ar, ai, tid, true);
    float2* fr = (float2*)(g_frames + (size_t)bf * NFFT);
    #pragma unroll
    for (int rep = 0; rep < 2; rep++) {
        int m = tid + rep * 256;
        int idx = AIDX(m);
        float y0 = ar[idx] * (1.0f / 1024.0f);
        float y1 = ai[idx] * (1.0f / 1024.0f);
        fr[m] = make_float2(__fmul_rn(y0, g_win[2*m]),
                            __fmul_rn(y1, g_win[2*m + 1]));
    }
}

// ---------------------------------------------------------------------------
__global__ void k_max() {
    int b   = blockIdx.x;
    int tid = threadIdx.x;
    __shared__ float red[1024];
    const float* au = g_audio + (size_t)b * LSIG;
    float m = 0.f;
    for (int i = tid; i < LSIG; i += 1024) m = fmaxf(m, fabsf(au[i]));
    red[tid] = m;
    __syncthreads();
    for (int s = 512; s > 0; s >>= 1) {
        if (tid < s) red[tid] = fmaxf(red[tid], red[tid + s]);
        __syncthreads();
    }
    if (tid == 0) g_maxv[b] = fmaxf(red[0], 1e-8f);
}

__global__ void k_final(float* __restrict__ out) {
    int i = blockIdx.x * blockDim.x + threadIdx.x;
    if (i >= OUT_AUDIO) return;
    int b = i >> 17;
    int t = i & (NSAMP - 1);
    float v = 0.f;
    if (t < LSIG)
        v = __fmul_rn(__fdiv_rn(g_audio[(size_t)b * LSIG + t], g_maxv[b]), 0.9f);
    out[i] = v;
}

// ---------------------------------------------------------------------------
extern "C" void kernel_launch(void* const* d_in, const int* in_sizes, int n_in,
                              void* d_out, int out_size) {
    const float* params = (const float*)d_in[0];
    float* out = (float*)d_out;
    float* fs_out = out + OUT_AUDIO;

    k_init_tables<<<4, 256>>>();
    k_fullspec<<<(OUT_FS + 255) / 256, 256>>>(params, fs_out);
    k_mag<<<(NTOT + 255) / 256, 256>>>(fs_out);
    k_init_phase<<<(NTOT + 255) / 256, 256>>>();

    const int NBF = GB * NFRAMES;
    // initial ISTFT from S0 -> frames (exact FFT)
    k_istft_frames_f32<<<NBF, 256>>>();
    // 32 GL iterations: exact FFT early, conflict-free radix-8 FFT from iter 4
    for (int it = 0; it < 32; it++) {
        k_ola<<<(GB * LSIG + 255) / 256, 256>>>();
        if (it < FAST_START)
            k_fused_update_istft<<<NBF, 256>>>();
        else
            k_fused_update_istft_fast<<<NBF, 256>>>();
    }
    // final OLA, then normalize
    k_ola<<<(GB * LSIG + 255) / 256, 256>>>();
    k_max<<<GB, 1024>>>();
    k_final<<<(OUT_AUDIO + 255) / 256, 256>>>(out);
}